// round 1
// baseline (speedup 1.0000x reference)
#include <cuda_runtime.h>
#include <math.h>

#define N_ 2048
#define D_ 512
#define K_ 65536

constexpr float TEMP_INV = 5.0f;   // 1 / 0.2
constexpr float CSHIFT   = 5.0f;   // |logit| <= 1/T = 5, exact bound
constexpr float EPS      = 1e-8f;

// Scratch (allocation-free rule: __device__ globals)
__device__ float g_inv_qn[N_];
__device__ float g_lpos[N_];
__device__ float g_inv_un[K_];
__device__ float g_S[N_];          // sum of exp(logit - C), seeded with positive term

__device__ __forceinline__ float warp_sum(float v) {
#pragma unroll
    for (int o = 16; o > 0; o >>= 1) v += __shfl_xor_sync(0xffffffffu, v, o);
    return v;
}

// ---------------------------------------------------------------------------
// Prep 1: per-row query/keys norms, positive logit, seed g_S
// one block (128 threads) per row; 512 floats = 128 float4
// ---------------------------------------------------------------------------
__global__ void prep_qk(const float* __restrict__ q, const float* __restrict__ k) {
    int n = blockIdx.x;
    int tid = threadIdx.x;
    const float4* q4 = (const float4*)(q + (size_t)n * D_);
    const float4* k4 = (const float4*)(k + (size_t)n * D_);
    float4 a = q4[tid];
    float4 b = k4[tid];
    float sq = a.x * a.x + a.y * a.y + a.z * a.z + a.w * a.w;
    float sk = b.x * b.x + b.y * b.y + b.z * b.z + b.w * b.w;
    float dp = a.x * b.x + a.y * b.y + a.z * b.z + a.w * b.w;

    __shared__ float s_sq[4], s_sk[4], s_dp[4];
    sq = warp_sum(sq); sk = warp_sum(sk); dp = warp_sum(dp);
    int wid = tid >> 5, lid = tid & 31;
    if (lid == 0) { s_sq[wid] = sq; s_sk[wid] = sk; s_dp[wid] = dp; }
    __syncthreads();
    if (tid == 0) {
        float tsq = s_sq[0] + s_sq[1] + s_sq[2] + s_sq[3];
        float tsk = s_sk[0] + s_sk[1] + s_sk[2] + s_sk[3];
        float tdp = s_dp[0] + s_dp[1] + s_dp[2] + s_dp[3];
        float qn = sqrtf(tsq);
        float kn = sqrtf(tsk);
        float lpos = tdp / fmaxf(qn * kn, EPS) * TEMP_INV;
        g_lpos[n] = lpos;
        g_inv_qn[n] = 1.0f / qn;
        g_S[n] = expf(lpos - CSHIFT);   // seed with positive term (overwrites every call)
    }
}

// ---------------------------------------------------------------------------
// Prep 2: queue row inverse norms. one block (128 threads) per queue row.
// ---------------------------------------------------------------------------
__global__ void prep_queue(const float* __restrict__ u) {
    int r = blockIdx.x;
    int tid = threadIdx.x;
    float4 a = ((const float4*)(u + (size_t)r * D_))[tid];
    float s = a.x * a.x + a.y * a.y + a.z * a.z + a.w * a.w;
    __shared__ float sm[4];
    s = warp_sum(s);
    int wid = tid >> 5, lid = tid & 31;
    if (lid == 0) sm[wid] = s;
    __syncthreads();
    if (tid == 0) {
        float t = sm[0] + sm[1] + sm[2] + sm[3];
        g_inv_un[r] = 1.0f / sqrtf(t);
    }
}

// ---------------------------------------------------------------------------
// Main: 64x64 tile GEMM over D=512, fused normalize -> exp -> row-sum.
// grid = (N/64, K/64); x = row tile (fast-varying) so concurrent CTAs share
// the same queue column tile and queue streams from DRAM once.
// ---------------------------------------------------------------------------
constexpr int BM = 64, BN = 64, BK = 16;

__global__ __launch_bounds__(256) void gemm_lse(const float* __restrict__ q,
                                                const float* __restrict__ u) {
    __shared__ float As[BK][BM];
    __shared__ float Bs[BK][BN];

    const int m0 = blockIdx.x * BM;
    const int n0 = blockIdx.y * BN;
    const int tid = threadIdx.x;
    const int tx = tid & 15;        // 0..15  column group
    const int ty = tid >> 4;        // 0..15  row group

    const int lr = tid >> 2;        // 0..63  load row
    const int lc = (tid & 3) * 4;   // 0,4,8,12

    const float* Ag = q + (size_t)(m0 + lr) * D_ + lc;
    const float* Bg = u + (size_t)(n0 + lr) * D_ + lc;

    float acc[4][4];
#pragma unroll
    for (int i = 0; i < 4; i++)
#pragma unroll
        for (int j = 0; j < 4; j++) acc[i][j] = 0.0f;

    for (int kk = 0; kk < D_; kk += BK) {
        float4 a = *(const float4*)(Ag + kk);
        float4 b = *(const float4*)(Bg + kk);
        As[lc + 0][lr] = a.x; As[lc + 1][lr] = a.y;
        As[lc + 2][lr] = a.z; As[lc + 3][lr] = a.w;
        Bs[lc + 0][lr] = b.x; Bs[lc + 1][lr] = b.y;
        Bs[lc + 2][lr] = b.z; Bs[lc + 3][lr] = b.w;
        __syncthreads();
#pragma unroll
        for (int p = 0; p < BK; p++) {
            float4 av = *(const float4*)&As[p][ty * 4];
            float4 bv = *(const float4*)&Bs[p][tx * 4];
            float ar[4] = {av.x, av.y, av.z, av.w};
            float br[4] = {bv.x, bv.y, bv.z, bv.w};
#pragma unroll
            for (int i = 0; i < 4; i++)
#pragma unroll
                for (int j = 0; j < 4; j++) acc[i][j] += ar[i] * br[j];
        }
        __syncthreads();
    }

    // Epilogue: normalize, exp, row partial sums
    float invq[4], invu[4];
#pragma unroll
    for (int i = 0; i < 4; i++) invq[i] = g_inv_qn[m0 + ty * 4 + i] * TEMP_INV;
#pragma unroll
    for (int j = 0; j < 4; j++) invu[j] = g_inv_un[n0 + tx * 4 + j];

    float rowsum[4];
#pragma unroll
    for (int i = 0; i < 4; i++) {
        float rs = 0.0f;
#pragma unroll
        for (int j = 0; j < 4; j++) {
            float l = acc[i][j] * invq[i] * invu[j];
            rs += __expf(l - CSHIFT);
        }
        rowsum[i] = rs;
    }

    // reduce 16 column-group partials per row in smem, then one atomic per row
    __shared__ float red[BM][16];
#pragma unroll
    for (int i = 0; i < 4; i++) red[ty * 4 + i][tx] = rowsum[i];
    __syncthreads();
    if (tid < BM) {
        float t = 0.0f;
#pragma unroll
        for (int c = 0; c < 16; c++) t += red[tid][c];
        atomicAdd(&g_S[m0 + tid], t);
    }
}

// ---------------------------------------------------------------------------
// Finalize: loss = mean(C + log(S_n) - lpos_n)
// ---------------------------------------------------------------------------
__global__ void finalize(float* __restrict__ out) {
    int tid = threadIdx.x;  // 256
    float local = 0.0f;
    for (int n = tid; n < N_; n += 256)
        local += CSHIFT + logf(g_S[n]) - g_lpos[n];
    __shared__ float red[256];
    red[tid] = local;
    __syncthreads();
    for (int s = 128; s > 0; s >>= 1) {
        if (tid < s) red[tid] += red[tid + s];
        __syncthreads();
    }
    if (tid == 0) out[0] = red[0] / (float)N_;
}

extern "C" void kernel_launch(void* const* d_in, const int* in_sizes, int n_in,
                              void* d_out, int out_size) {
    const float* query = (const float*)d_in[0];
    const float* keys  = (const float*)d_in[1];
    const float* queue = (const float*)d_in[2];
    float* out = (float*)d_out;

    prep_qk<<<N_, 128>>>(query, keys);
    prep_queue<<<K_, 128>>>(queue);
    dim3 grid(N_ / BM, K_ / BN);  // x = row tile (fast) -> queue tiles shared in L2
    gemm_lse<<<grid, 256>>>(query, queue);
    finalize<<<1, 256>>>(out);
}

// round 4
// speedup vs baseline: 7.6146x; 7.6146x over previous
#include <cuda_runtime.h>
#include <cuda_bf16.h>
#include <math.h>
#include <stdint.h>

#define N_ 2048
#define D_ 512
#define K_ 65536

constexpr float TEMP_INV = 5.0f;
constexpr float CSHIFT   = 5.0f;
constexpr float EPS      = 1e-8f;

// ---------------- device scratch (allocation-free rule) ----------------
__device__ float g_inv_qn[N_];
__device__ float g_lpos[N_];
__device__ float g_S[N_];
__device__ __nv_bfloat16 g_Qn[N_ * D_];   // 2 MB  (query * 5*inv_qn)
__device__ __nv_bfloat16 g_Un[K_ * D_];   // 64 MB (queue * inv_un)

// ---------------- PTX helpers ----------------
__device__ __forceinline__ uint32_t smem_u32(const void* p) {
    uint32_t a;
    asm("{ .reg .u64 t; cvta.to.shared.u64 t, %1; cvt.u32.u64 %0, t; }" : "=r"(a) : "l"(p));
    return a;
}

#define CP_ASYNC16(dst, src) \
    asm volatile("cp.async.cg.shared.global [%0], [%1], 16;\n" :: "r"(dst), "l"(src))
#define CP_COMMIT() asm volatile("cp.async.commit_group;\n" ::: "memory")
#define CP_WAIT(n)  asm volatile("cp.async.wait_group %0;\n" :: "n"(n) : "memory")

#define LDSM4(R0, R1, R2, R3, addr) \
    asm volatile("ldmatrix.sync.aligned.m8n8.x4.shared.b16 {%0,%1,%2,%3}, [%4];" \
        : "=r"(R0), "=r"(R1), "=r"(R2), "=r"(R3) : "r"(addr))

#define MMA16816(D, A, B0, B1) \
    asm volatile("mma.sync.aligned.m16n8k16.row.col.f32.bf16.bf16.f32 " \
        "{%0,%1,%2,%3}, {%4,%5,%6,%7}, {%8,%9}, {%0,%1,%2,%3};" \
        : "+f"((D)[0]), "+f"((D)[1]), "+f"((D)[2]), "+f"((D)[3]) \
        : "r"((A)[0]), "r"((A)[1]), "r"((A)[2]), "r"((A)[3]), "r"(B0), "r"(B1))

__device__ __forceinline__ float warp_sum(float v) {
#pragma unroll
    for (int o = 16; o > 0; o >>= 1) v += __shfl_xor_sync(0xffffffffu, v, o);
    return v;
}

// ---------------------------------------------------------------------------
// Prep 1: q/k norms, l_pos, seed g_S, write Qn = bf16(q * 5*inv_qn)
// ---------------------------------------------------------------------------
__global__ void prep_qk(const float* __restrict__ q, const float* __restrict__ k) {
    int n = blockIdx.x;
    int tid = threadIdx.x;  // 128
    float4 a = ((const float4*)(q + (size_t)n * D_))[tid];
    float4 b = ((const float4*)(k + (size_t)n * D_))[tid];
    float sq = a.x * a.x + a.y * a.y + a.z * a.z + a.w * a.w;
    float sk = b.x * b.x + b.y * b.y + b.z * b.z + b.w * b.w;
    float dp = a.x * b.x + a.y * b.y + a.z * b.z + a.w * b.w;

    __shared__ float s_sq[4], s_sk[4], s_dp[4];
    __shared__ float s_scale;
    sq = warp_sum(sq); sk = warp_sum(sk); dp = warp_sum(dp);
    int wid = tid >> 5, lid = tid & 31;
    if (lid == 0) { s_sq[wid] = sq; s_sk[wid] = sk; s_dp[wid] = dp; }
    __syncthreads();
    if (tid == 0) {
        float tsq = s_sq[0] + s_sq[1] + s_sq[2] + s_sq[3];
        float tsk = s_sk[0] + s_sk[1] + s_sk[2] + s_sk[3];
        float tdp = s_dp[0] + s_dp[1] + s_dp[2] + s_dp[3];
        float qn = sqrtf(tsq), kn = sqrtf(tsk);
        float lpos = tdp / fmaxf(qn * kn, EPS) * TEMP_INV;
        g_lpos[n] = lpos;
        g_inv_qn[n] = 1.0f / qn;
        g_S[n] = expf(lpos - CSHIFT);
        s_scale = TEMP_INV / qn;
    }
    __syncthreads();
    float s = s_scale;
    __nv_bfloat162* dst = (__nv_bfloat162*)(g_Qn + (size_t)n * D_);
    dst[tid * 2 + 0] = __floats2bfloat162_rn(a.x * s, a.y * s);
    dst[tid * 2 + 1] = __floats2bfloat162_rn(a.z * s, a.w * s);
}

// ---------------------------------------------------------------------------
// Prep 2: queue norms, write Un = bf16(u * inv_un)
// ---------------------------------------------------------------------------
__global__ void prep_queue(const float* __restrict__ u) {
    int r = blockIdx.x;
    int tid = threadIdx.x;  // 128
    float4 a = ((const float4*)(u + (size_t)r * D_))[tid];
    float s = a.x * a.x + a.y * a.y + a.z * a.z + a.w * a.w;
    __shared__ float sm[4];
    __shared__ float s_scale;
    s = warp_sum(s);
    int wid = tid >> 5, lid = tid & 31;
    if (lid == 0) sm[wid] = s;
    __syncthreads();
    if (tid == 0) s_scale = rsqrtf(sm[0] + sm[1] + sm[2] + sm[3]);
    __syncthreads();
    float sc = s_scale;
    __nv_bfloat162* dst = (__nv_bfloat162*)(g_Un + (size_t)r * D_);
    dst[tid * 2 + 0] = __floats2bfloat162_rn(a.x * sc, a.y * sc);
    dst[tid * 2 + 1] = __floats2bfloat162_rn(a.z * sc, a.w * sc);
}

// ---------------------------------------------------------------------------
// Main GEMM+LSE via mma.sync.m16n8k16 (bf16 -> fp32).
// CTA tile: 128 queue rows (M) x 128 query rows (N), BK=32, 3-stage cp.async.
// Smem rows padded to 80B (stride 80 mod 128 -> conflict-free ldmatrix).
// Warp layout 2(M) x 4(N), warp tile 64x32.
// Epilogue: exp(l-5) in regs, butterfly reduce over M, atomicAdd(g_S).
// ---------------------------------------------------------------------------
constexpr int BM = 128, BN = 128, BK = 32;
constexpr uint32_t ROWB = 80;                    // padded row bytes (32 bf16 + 16B pad)
constexpr uint32_t A_BYTES = 128 * ROWB;         // 10240
constexpr uint32_t STAGE_BYTES = 2 * A_BYTES;    // A + B = 20480
constexpr uint32_t SMEM_TOTAL = 3 * STAGE_BYTES; // 61440
constexpr int NIT = D_ / BK;                     // 16

__device__ __forceinline__ void load_stage(uint32_t sb, int st, int m0, int n0,
                                           int kk, int tid) {
    uint32_t base = sb + st * STAGE_BYTES;
#pragma unroll
    for (int i = 0; i < 4; i++) {
        int id = tid + i * 256;          // 0..1023 : first 512 = A, rest = B
        int isB = (id >= 512);
        int l2 = id - (isB ? 512 : 0);
        int row = l2 >> 2, c = l2 & 3;   // row 0..127, 16B chunk 0..3
        const __nv_bfloat16* src =
            (isB ? g_Qn + (size_t)(n0 + row) * D_ : g_Un + (size_t)(m0 + row) * D_)
            + kk + c * 8;
        uint32_t dst = base + (isB ? A_BYTES : 0u) + row * ROWB + c * 16u;
        CP_ASYNC16(dst, src);
    }
}

__global__ __launch_bounds__(256) void gemm_lse_mma() {
    extern __shared__ __align__(128) char smem[];
    const uint32_t sb = smem_u32(smem);
    const int tid = threadIdx.x;
    const int wid = tid >> 5, lane = tid & 31;
    const int n0 = blockIdx.x * BN;      // query tile (fast -> Un shared via L2)
    const int m0 = blockIdx.y * BM;      // queue tile
    const int warp_m = wid & 1;          // 0..1 -> 64 rows
    const int warp_n = wid >> 1;         // 0..3 -> 32 cols

    float acc[4][4][4];                  // [mtile16][ntile8][frag]
#pragma unroll
    for (int i = 0; i < 4; i++)
#pragma unroll
        for (int j = 0; j < 4; j++)
#pragma unroll
            for (int r = 0; r < 4; r++) acc[i][j][r] = 0.0f;

    load_stage(sb, 0, m0, n0, 0, tid);  CP_COMMIT();
    load_stage(sb, 1, m0, n0, BK, tid); CP_COMMIT();

    // per-warp ldmatrix base offsets (lane&15 = row-within-16, lane>>4 = k-half)
    const uint32_t aOff = (warp_m * 64 + (lane & 15)) * ROWB + ((lane >> 4) * 16);
    const uint32_t bOff = A_BYTES + (warp_n * 32 + (lane & 15)) * ROWB + ((lane >> 4) * 16);

    for (int it = 0; it < NIT; it++) {
        if (it == NIT - 1) { CP_WAIT(0); } else { CP_WAIT(1); }
        __syncthreads();
        const uint32_t stb = sb + (it % 3) * STAGE_BYTES;
#pragma unroll
        for (int ks = 0; ks < 2; ks++) {      // two k16 steps per BK=32
            uint32_t a[4][4], b[2][4];
#pragma unroll
            for (int mt = 0; mt < 4; mt++)
                LDSM4(a[mt][0], a[mt][1], a[mt][2], a[mt][3],
                      stb + aOff + mt * 16 * ROWB + ks * 32);
#pragma unroll
            for (int ng = 0; ng < 2; ng++)
                LDSM4(b[ng][0], b[ng][1], b[ng][2], b[ng][3],
                      stb + bOff + ng * 16 * ROWB + ks * 32);
#pragma unroll
            for (int mt = 0; mt < 4; mt++) {
#pragma unroll
                for (int ng = 0; ng < 2; ng++) {
                    MMA16816(acc[mt][2 * ng + 0], a[mt], b[ng][0], b[ng][2]);
                    MMA16816(acc[mt][2 * ng + 1], a[mt], b[ng][1], b[ng][3]);
                }
            }
        }
        if (it + 2 < NIT) {
            load_stage(sb, (it + 2) % 3, m0, n0, (it + 2) * BK, tid);
            CP_COMMIT();
        }
    }

    // Epilogue: exp -> reduce over 64 warp rows -> 8 atomics per warp quad
#pragma unroll
    for (int j = 0; j < 4; j++) {             // ntile8
        float s0 = 0.0f, s1 = 0.0f;
#pragma unroll
        for (int mt = 0; mt < 4; mt++) {
            s0 += __expf(acc[mt][j][0] - CSHIFT) + __expf(acc[mt][j][2] - CSHIFT);
            s1 += __expf(acc[mt][j][1] - CSHIFT) + __expf(acc[mt][j][3] - CSHIFT);
        }
#pragma unroll
        for (int o = 4; o <= 16; o <<= 1) {   // reduce over row groups (lane bits 2..4)
            s0 += __shfl_xor_sync(0xffffffffu, s0, o);
            s1 += __shfl_xor_sync(0xffffffffu, s1, o);
        }
        if (lane < 4) {
            int col = n0 + warp_n * 32 + j * 8 + lane * 2;
            atomicAdd(&g_S[col], s0);
            atomicAdd(&g_S[col + 1], s1);
        }
    }
}

// ---------------------------------------------------------------------------
// Finalize: loss = mean(C + log(S_n) - lpos_n)
// ---------------------------------------------------------------------------
__global__ void finalize(float* __restrict__ out) {
    int tid = threadIdx.x;  // 256
    float local = 0.0f;
    for (int n = tid; n < N_; n += 256)
        local += CSHIFT + logf(g_S[n]) - g_lpos[n];
    __shared__ float red[256];
    red[tid] = local;
    __syncthreads();
    for (int s = 128; s > 0; s >>= 1) {
        if (tid < s) red[tid] += red[tid + s];
        __syncthreads();
    }
    if (tid == 0) out[0] = red[0] / (float)N_;
}

extern "C" void kernel_launch(void* const* d_in, const int* in_sizes, int n_in,
                              void* d_out, int out_size) {
    const float* query = (const float*)d_in[0];
    const float* keys  = (const float*)d_in[1];
    const float* queue = (const float*)d_in[2];
    float* out = (float*)d_out;

    cudaFuncSetAttribute(gemm_lse_mma, cudaFuncAttributeMaxDynamicSharedMemorySize, SMEM_TOTAL);

    prep_qk<<<N_, 128>>>(query, keys);
    prep_queue<<<K_, 128>>>(queue);
    dim3 grid(N_ / BN, K_ / BM);   // 16 x 512, x fast -> Un tiles shared in L2
    gemm_lse_mma<<<grid, 256, SMEM_TOTAL>>>();
    finalize<<<1, 256>>>(out);
}